// round 7
// baseline (speedup 1.0000x reference)
#include <cuda_runtime.h>

#define NN   100000
#define NE   1600000
#define NEL  6400000
#define EPSV 1e-5

#define RPAD(x) (((x) + 4095) & ~4095)
#define RP_G  RPAD(NN)
#define RP_LG RPAD(NE)

// padded slot capacities (each row padded to multiple of 4 => +3 max per row)
#define SL_G_CAP  (NE  + 3 * RP_G)
#define SL_LG_CAP (NEL + 3 * RP_LG)

// ---------------- scratch (device globals; no allocation allowed) ----------
__device__ float  g_yx[(size_t)NN * 16];
__device__ float  g_x1[(size_t)NN * 16];
__device__ float  g_x2[(size_t)NN * 16];
__device__ float  g_x4[(size_t)NN * 16];
__device__ float  g_xt[(size_t)NN * 16];
__device__ float  g_ya[(size_t)NE * 16];
__device__ float  g_y1[(size_t)NE * 16];
__device__ float  g_y2[(size_t)NE * 16];
__device__ float  g_y4[(size_t)NE * 16];
__device__ float  g_t3[(size_t)NE * 16];
__device__ int    g_cnt_g[RP_G];
__device__ int    g_rowptr_g[RP_G + 1];     // padded CSR
__device__ int2   g_slots_g[SL_G_CAP];      // {src, edge_id}, -1 = padding
__device__ int    g_bsum_g[2048];
__device__ int    g_perm_g[RP_G];
__device__ int    g_cnt_lg[RP_LG];
__device__ int    g_rowptr_lg[RP_LG + 1];   // padded CSR
__device__ int    g_slots_lg[SL_LG_CAP];    // src, -1 = padding
__device__ int    g_bsum_lg[2048];
__device__ int    g_perm_lg[RP_LG];
__device__ int    g_bins[256];              // [0:64) bcnt_g, [64:128) cursor_g, +128 for lg
__device__ double g_stats[64];
__device__ float  g_coef[64];

// ---------------- CSR build kernels ---------------------------------------

__global__ void __launch_bounds__(256) k_hist(
    const int* __restrict__ dst, int* __restrict__ cnt, int nE)
{
    long t = (long)blockIdx.x * 256 + threadIdx.x;
    if (t >= nE) return;
    atomicAdd(&cnt[__ldg(dst + t)], 1);
}

#define PAD4(v) (((v) + 3) & ~3)

// per-block sum of PADDED counts over 4096 rows
__global__ void __launch_bounds__(256) k_scan1(
    const int* __restrict__ cnt, int* __restrict__ bsum)
{
    __shared__ int sh[256];
    int b = blockIdx.x, tid = threadIdx.x;
    const int4* c4 = reinterpret_cast<const int4*>(cnt);
    long base = (long)b * 1024 + (long)tid * 4;
    int s = 0;
    #pragma unroll
    for (int i = 0; i < 4; i++) {
        int4 v = __ldg(c4 + base + i);
        s += PAD4(v.x) + PAD4(v.y) + PAD4(v.z) + PAD4(v.w);
    }
    sh[tid] = s; __syncthreads();
    for (int off = 128; off > 0; off >>= 1) {
        if (tid < off) sh[tid] += sh[tid + off];
        __syncthreads();
    }
    if (tid == 0) bsum[b] = sh[0];
}

__global__ void __launch_bounds__(1024) k_scan2(int* __restrict__ bsum, int nb)
{
    __shared__ int s[2048];
    int tid = threadIdx.x;
    s[tid]        = (tid        < nb) ? bsum[tid]        : 0;
    s[tid + 1024] = (tid + 1024 < nb) ? bsum[tid + 1024] : 0;
    int off = 1;
    for (int d = 1024; d > 0; d >>= 1) {
        __syncthreads();
        if (tid < d) {
            int ai = off * (2 * tid + 1) - 1;
            int bi = off * (2 * tid + 2) - 1;
            s[bi] += s[ai];
        }
        off <<= 1;
    }
    if (tid == 0) s[2047] = 0;
    for (int d = 1; d < 2048; d <<= 1) {
        off >>= 1;
        __syncthreads();
        if (tid < d) {
            int ai = off * (2 * tid + 1) - 1;
            int bi = off * (2 * tid + 2) - 1;
            int t = s[ai]; s[ai] = s[bi]; s[bi] += t;
        }
    }
    __syncthreads();
    if (tid        < nb) bsum[tid]        = s[tid];
    if (tid + 1024 < nb) bsum[tid + 1024] = s[tid + 1024];
}

// final exclusive scan of PADDED counts -> rowptr
__global__ void __launch_bounds__(256) k_scan3(
    const int* __restrict__ cnt, const int* __restrict__ bsum,
    int* __restrict__ rowptr, int RP)
{
    __shared__ int sh[256];
    int b = blockIdx.x, tid = threadIdx.x;
    const int4* c4 = reinterpret_cast<const int4*>(cnt);
    long base4 = (long)b * 1024 + (long)tid * 4;
    int vals[16];
    int tsum = 0;
    #pragma unroll
    for (int i = 0; i < 4; i++) {
        int4 v = __ldg(c4 + base4 + i);
        vals[i * 4 + 0] = PAD4(v.x); vals[i * 4 + 1] = PAD4(v.y);
        vals[i * 4 + 2] = PAD4(v.z); vals[i * 4 + 3] = PAD4(v.w);
        tsum += vals[i*4+0] + vals[i*4+1] + vals[i*4+2] + vals[i*4+3];
    }
    sh[tid] = tsum; __syncthreads();
    for (int off = 1; off < 256; off <<= 1) {
        int t2 = (tid >= off) ? sh[tid - off] : 0;
        __syncthreads();
        sh[tid] += t2;
        __syncthreads();
    }
    int run = __ldg(bsum + b) + sh[tid] - tsum;
    long base = (long)b * 4096 + (long)tid * 16;
    #pragma unroll
    for (int i = 0; i < 16; i++) { rowptr[base + i] = run; run += vals[i]; }
    if (b == gridDim.x - 1 && tid == 255) rowptr[RP] = run;
}

// ---- degree-bucket permutation (counting sort by degree, 64 bins) ----

__global__ void __launch_bounds__(256) k_permhist(
    const int* __restrict__ cnt, int* __restrict__ bcnt, int R)
{
    long t = (long)blockIdx.x * 256 + threadIdx.x;
    if (t >= R) return;
    int d = min(__ldg(cnt + t), 63);
    atomicAdd(&bcnt[d], 1);
}

// exclusive scan of 64 bin counts -> cursor[64..127]
__global__ void k_permscan(int* __restrict__ bins)
{
    __shared__ int sh[64];
    int tid = threadIdx.x;    // 64 threads
    int v = bins[tid];
    sh[tid] = v; __syncthreads();
    int acc = 0;
    for (int i = 0; i < 64; i++) { if (i < tid) acc += sh[i]; }  // small, fine
    bins[64 + tid] = acc;
}

__global__ void __launch_bounds__(256) k_permfill(
    const int* __restrict__ cnt, int* __restrict__ cursor,
    int* __restrict__ perm, int R)
{
    long t = (long)blockIdx.x * 256 + threadIdx.x;
    if (t >= R) return;
    int d = min(__ldg(cnt + t), 63);
    int pos = atomicAdd(&cursor[d], 1);
    perm[pos] = (int)t;
}

// ---- slot fill (padding slots pre-set to -1 via memset 0xFF) ----

__global__ void __launch_bounds__(256) k_fill_lg(
    const int* __restrict__ src, const int* __restrict__ dst,
    const int* __restrict__ rowptr, int* __restrict__ cnt,
    int* __restrict__ slots, int nE)
{
    long t = (long)blockIdx.x * 256 + threadIdx.x;
    if (t >= nE) return;
    int d = __ldg(dst + t);
    int p = __ldg(rowptr + d) + atomicAdd(&cnt[d], 1);
    slots[p] = __ldg(src + t);
}

__global__ void __launch_bounds__(256) k_fill_g(
    const int* __restrict__ src, const int* __restrict__ dst,
    const int* __restrict__ rowptr, int* __restrict__ cnt,
    int2* __restrict__ slots, int nE)
{
    long t = (long)blockIdx.x * 256 + threadIdx.x;
    if (t >= nE) return;
    int d = __ldg(dst + t);
    int p = __ldg(rowptr + d) + atomicAdd(&cnt[d], 1);
    slots[p] = make_int2(__ldg(src + t), (int)t);
}

// ---------------- SpMM (pull mode, padded CSR, degree-sorted, no atomics) --

#define F4(p) reinterpret_cast<const float4*>(p)

__device__ __forceinline__ void acc4(float4& a, float4 v) {
    a.x += v.x; a.y += v.y; a.z += v.z; a.w += v.w;
}

// out[r] = sum z[slots[e]] ; int slots, padded to 4, sentinel -1
__global__ void __launch_bounds__(256) k_spmm_csr(
    const float* __restrict__ z, const int* __restrict__ rowptr,
    const int* __restrict__ slots, const int* __restrict__ perm,
    float* __restrict__ out, int R)
{
    long t = (long)blockIdx.x * 256 + threadIdx.x;
    int i = (int)(t >> 2);
    if (i >= R) return;
    int c = (int)(t & 3);
    int r = __ldg(perm + i);
    int e   = __ldg(rowptr + r);
    int end = __ldg(rowptr + r + 1);
    const int4* sl4 = reinterpret_cast<const int4*>(slots);
    float4 acc = make_float4(0.f, 0.f, 0.f, 0.f);
    for (; e < end; e += 4) {
        int4 s = __ldg(sl4 + (e >> 2));
        float4 v0 = __ldg(F4(z) + (((size_t)max(s.x, 0) << 2) + c));
        float4 v1 = __ldg(F4(z) + (((size_t)max(s.y, 0) << 2) + c));
        float4 v2 = __ldg(F4(z) + (((size_t)max(s.z, 0) << 2) + c));
        float4 v3 = __ldg(F4(z) + (((size_t)max(s.w, 0) << 2) + c));
        if (s.x >= 0) acc4(acc, v0);
        if (s.y >= 0) acc4(acc, v1);
        if (s.z >= 0) acc4(acc, v2);
        if (s.w >= 0) acc4(acc, v3);
    }
    reinterpret_cast<float4*>(out)[((size_t)r << 2) + c] = acc;
}

// out[r] = sum z[slots[e].x] ; int2 slots, padded, sentinel {-1,-1}
__global__ void __launch_bounds__(256) k_spmm_csr2(
    const float* __restrict__ z, const int* __restrict__ rowptr,
    const int2* __restrict__ slots, const int* __restrict__ perm,
    float* __restrict__ out, int R)
{
    long t = (long)blockIdx.x * 256 + threadIdx.x;
    int i = (int)(t >> 2);
    if (i >= R) return;
    int c = (int)(t & 3);
    int r = __ldg(perm + i);
    int e   = __ldg(rowptr + r);
    int end = __ldg(rowptr + r + 1);
    const int4* sl4 = reinterpret_cast<const int4*>(slots);  // 2 int2 per int4
    float4 acc = make_float4(0.f, 0.f, 0.f, 0.f);
    for (; e < end; e += 4) {
        int4 a = __ldg(sl4 + (e >> 1));
        int4 b = __ldg(sl4 + (e >> 1) + 1);
        float4 v0 = __ldg(F4(z) + (((size_t)max(a.x, 0) << 2) + c));
        float4 v1 = __ldg(F4(z) + (((size_t)max(a.z, 0) << 2) + c));
        float4 v2 = __ldg(F4(z) + (((size_t)max(b.x, 0) << 2) + c));
        float4 v3 = __ldg(F4(z) + (((size_t)max(b.z, 0) << 2) + c));
        if (a.x >= 0) acc4(acc, v0);
        if (a.z >= 0) acc4(acc, v1);
        if (b.x >= 0) acc4(acc, v2);
        if (b.z >= 0) acc4(acc, v3);
    }
    reinterpret_cast<float4*>(out)[((size_t)r << 2) + c] = acc;
}

// node pass1: x1[r] = sum x[src], yx[r] = sum y[eid]
__global__ void __launch_bounds__(256) k_node_pass1(
    const float* __restrict__ x, const float* __restrict__ y,
    const int* __restrict__ rowptr, const int2* __restrict__ slots,
    const int* __restrict__ perm,
    float* __restrict__ outx1, float* __restrict__ outyx, int R)
{
    long t = (long)blockIdx.x * 256 + threadIdx.x;
    int i = (int)(t >> 2);
    if (i >= R) return;
    int c = (int)(t & 3);
    int r = __ldg(perm + i);
    int e   = __ldg(rowptr + r);
    int end = __ldg(rowptr + r + 1);
    const int4* sl4 = reinterpret_cast<const int4*>(slots);
    float4 ax = make_float4(0.f, 0.f, 0.f, 0.f);
    float4 ay = make_float4(0.f, 0.f, 0.f, 0.f);
    for (; e < end; e += 4) {
        int4 a = __ldg(sl4 + (e >> 1));
        int4 b = __ldg(sl4 + (e >> 1) + 1);
        float4 vx0 = __ldg(F4(x) + (((size_t)max(a.x, 0) << 2) + c));
        float4 vy0 = __ldg(F4(y) + (((size_t)max(a.y, 0) << 2) + c));
        float4 vx1 = __ldg(F4(x) + (((size_t)max(a.z, 0) << 2) + c));
        float4 vy1 = __ldg(F4(y) + (((size_t)max(a.w, 0) << 2) + c));
        float4 vx2 = __ldg(F4(x) + (((size_t)max(b.x, 0) << 2) + c));
        float4 vy2 = __ldg(F4(y) + (((size_t)max(b.y, 0) << 2) + c));
        float4 vx3 = __ldg(F4(x) + (((size_t)max(b.z, 0) << 2) + c));
        float4 vy3 = __ldg(F4(y) + (((size_t)max(b.w, 0) << 2) + c));
        if (a.x >= 0) { acc4(ax, vx0); acc4(ay, vy0); }
        if (a.z >= 0) { acc4(ax, vx1); acc4(ay, vy1); }
        if (b.x >= 0) { acc4(ax, vx2); acc4(ay, vy2); }
        if (b.z >= 0) { acc4(ax, vx3); acc4(ay, vy3); }
    }
    reinterpret_cast<float4*>(outx1)[((size_t)r << 2) + c] = ax;
    reinterpret_cast<float4*>(outyx)[((size_t)r << 2) + c] = ay;
}

// line pass1: y1[r] = sum y[s], ya[r] = sum x[eid2nid[s]]
__global__ void __launch_bounds__(256) k_line_pass1(
    const float* __restrict__ y, const float* __restrict__ x,
    const int* __restrict__ eid2nid,
    const int* __restrict__ rowptr, const int* __restrict__ slots,
    const int* __restrict__ perm,
    float* __restrict__ outy1, float* __restrict__ outya, int R)
{
    long t = (long)blockIdx.x * 256 + threadIdx.x;
    int i = (int)(t >> 2);
    if (i >= R) return;
    int c = (int)(t & 3);
    int r = __ldg(perm + i);
    int e   = __ldg(rowptr + r);
    int end = __ldg(rowptr + r + 1);
    const int4* sl4 = reinterpret_cast<const int4*>(slots);
    float4 ay  = make_float4(0.f, 0.f, 0.f, 0.f);
    float4 axy = make_float4(0.f, 0.f, 0.f, 0.f);
    for (; e < end; e += 4) {
        int4 s = __ldg(sl4 + (e >> 2));
        int n0 = __ldg(eid2nid + max(s.x, 0));
        int n1 = __ldg(eid2nid + max(s.y, 0));
        int n2 = __ldg(eid2nid + max(s.z, 0));
        int n3 = __ldg(eid2nid + max(s.w, 0));
        float4 vy0 = __ldg(F4(y) + (((size_t)max(s.x, 0) << 2) + c));
        float4 vy1 = __ldg(F4(y) + (((size_t)max(s.y, 0) << 2) + c));
        float4 vy2 = __ldg(F4(y) + (((size_t)max(s.z, 0) << 2) + c));
        float4 vy3 = __ldg(F4(y) + (((size_t)max(s.w, 0) << 2) + c));
        float4 vx0 = __ldg(F4(x) + (((size_t)n0 << 2) + c));
        float4 vx1 = __ldg(F4(x) + (((size_t)n1 << 2) + c));
        float4 vx2 = __ldg(F4(x) + (((size_t)n2 << 2) + c));
        float4 vx3 = __ldg(F4(x) + (((size_t)n3 << 2) + c));
        if (s.x >= 0) { acc4(ay, vy0); acc4(axy, vx0); }
        if (s.y >= 0) { acc4(ay, vy1); acc4(axy, vx1); }
        if (s.z >= 0) { acc4(ay, vy2); acc4(axy, vx2); }
        if (s.w >= 0) { acc4(ay, vy3); acc4(axy, vx3); }
    }
    reinterpret_cast<float4*>(outy1)[((size_t)r << 2) + c] = ay;
    reinterpret_cast<float4*>(outya)[((size_t)r << 2) + c] = axy;
}

// ---------------- combine + BN ---------------------------------------------

__global__ void __launch_bounds__(256) k_combine(
    const float* __restrict__ z0, const float* __restrict__ deg,
    const float* __restrict__ t2p, const float* __restrict__ t3p,
    const float* __restrict__ t4p, const float* __restrict__ t5p,
    const float* __restrict__ W, const float* __restrict__ B,
    float* __restrict__ out, double* __restrict__ stats, int n)
{
    __shared__ float4 sW[768];
    __shared__ float  sB[32];
    __shared__ float  sRed[32];
    int tid = threadIdx.x;
    const float4* W4 = reinterpret_cast<const float4*>(W);
    for (int i = tid; i < 768; i += 256) sW[i] = W4[i];
    if (tid < 32) {
        float b = 0.f;
        #pragma unroll
        for (int t = 0; t < 6; t++) b += B[t * 32 + tid];
        sB[tid] = b;
        sRed[tid] = 0.f;
    }
    __syncthreads();

    long r = (long)blockIdx.x * 256 + tid;
    if (r < (long)n) {
        float acc[32];
        #pragma unroll
        for (int j = 0; j < 32; j++) acc[j] = sB[j];
        float dg = __ldg(deg + r);
        #pragma unroll
        for (int t = 0; t < 6; t++) {
            const float* zp = (t <= 1) ? z0 : (t == 2 ? t2p : (t == 3 ? t3p : (t == 4 ? t4p : t5p)));
            const float4* z4p = F4(zp) + ((size_t)r << 2);
            float4 a0 = __ldg(z4p + 0);
            float4 a1 = __ldg(z4p + 1);
            float4 a2 = __ldg(z4p + 2);
            float4 a3 = __ldg(z4p + 3);
            if (t == 1) {
                a0.x *= dg; a0.y *= dg; a0.z *= dg; a0.w *= dg;
                a1.x *= dg; a1.y *= dg; a1.z *= dg; a1.w *= dg;
                a2.x *= dg; a2.y *= dg; a2.z *= dg; a2.w *= dg;
                a3.x *= dg; a3.y *= dg; a3.z *= dg; a3.w *= dg;
            }
            #pragma unroll
            for (int j = 0; j < 32; j++) {
                const float4* w = &sW[(t * 32 + j) * 4];
                float4 w0 = w[0], w1 = w[1], w2 = w[2], w3 = w[3];
                float s = acc[j];
                s += a0.x * w0.x + a0.y * w0.y + a0.z * w0.z + a0.w * w0.w;
                s += a1.x * w1.x + a1.y * w1.y + a1.z * w1.z + a1.w * w1.w;
                s += a2.x * w2.x + a2.y * w2.y + a2.z * w2.z + a2.w * w2.w;
                s += a3.x * w3.x + a3.y * w3.y + a3.z * w3.z + a3.w * w3.w;
                acc[j] = s;
            }
        }
        float h[16];
        #pragma unroll
        for (int j = 0; j < 16; j++) h[j] = acc[j] + fmaxf(acc[j + 16], 0.f);
        float4* o = reinterpret_cast<float4*>(out) + ((size_t)r << 2);
        o[0] = make_float4(h[0], h[1], h[2], h[3]);
        o[1] = make_float4(h[4], h[5], h[6], h[7]);
        o[2] = make_float4(h[8], h[9], h[10], h[11]);
        o[3] = make_float4(h[12], h[13], h[14], h[15]);
        #pragma unroll
        for (int c = 0; c < 16; c++) {
            atomicAdd(&sRed[c], h[c]);
            atomicAdd(&sRed[16 + c], h[c] * h[c]);
        }
    }
    __syncthreads();
    if (tid < 32) atomicAdd(&stats[tid], (double)sRed[tid]);
}

__global__ void k_bnprep(const double* __restrict__ stats, const float* __restrict__ w,
                         const float* __restrict__ b, float* __restrict__ coef, double n)
{
    int c = threadIdx.x;
    if (c >= 16) return;
    double m   = stats[c] / n;
    double var = stats[16 + c] / n - m * m;
    double s   = (double)w[c] / sqrt(var + (double)EPSV);
    coef[c]      = (float)s;
    coef[16 + c] = (float)((double)b[c] - m * s);
}

__global__ void __launch_bounds__(256) k_bn(
    float* __restrict__ h, const float* __restrict__ coef, long n4)
{
    long t = (long)blockIdx.x * 256 + threadIdx.x;
    if (t >= n4) return;
    int c = (int)(t & 3);
    float4 sc = reinterpret_cast<const float4*>(coef)[c];
    float4 sh = reinterpret_cast<const float4*>(coef)[4 + c];
    float4 v = reinterpret_cast<float4*>(h)[t];
    v.x = v.x * sc.x + sh.x;
    v.y = v.y * sc.y + sh.y;
    v.z = v.z * sc.z + sh.z;
    v.w = v.w * sc.w + sh.w;
    reinterpret_cast<float4*>(h)[t] = v;
}

// ---------------- host -----------------------------------------------------

static inline int cdiv(long a, int b) { return (int)((a + (long)b - 1) / b); }

extern "C" void kernel_launch(void* const* d_in, const int* in_sizes, int n_in,
                              void* d_out, int out_size)
{
    const float* x      = (const float*)d_in[0];
    const float* y      = (const float*)d_in[1];
    const float* deg_g  = (const float*)d_in[2];
    const float* deg_lg = (const float*)d_in[3];
    const float* thW    = (const float*)d_in[4];
    const float* thB    = (const float*)d_in[5];
    const float* gmW    = (const float*)d_in[6];
    const float* gmB    = (const float*)d_in[7];
    const float* bnxw   = (const float*)d_in[8];
    const float* bnxb   = (const float*)d_in[9];
    const float* bnyw   = (const float*)d_in[10];
    const float* bnyb   = (const float*)d_in[11];
    const int* src_g    = (const int*)d_in[12];
    const int* dst_g    = (const int*)d_in[13];
    const int* src_lg   = (const int*)d_in[14];
    const int* dst_lg   = (const int*)d_in[15];
    const int* eid      = (const int*)d_in[16];

    int N  = in_sizes[2];
    int E  = in_sizes[3];
    int EL = in_sizes[14];

    float *p_yx, *p_x1, *p_x2, *p_x4, *p_xt;
    float *p_ya, *p_y1, *p_y2, *p_y4, *p_t3, *p_coef;
    int *p_cnt_g, *p_rp_g, *p_bs_g, *p_cnt_lg, *p_rp_lg, *p_bs_lg, *p_slots_lg;
    int *p_perm_g, *p_perm_lg, *p_bins;
    int2* p_slots_g;
    double* p_stats;
    cudaGetSymbolAddress((void**)&p_yx, g_yx);
    cudaGetSymbolAddress((void**)&p_x1, g_x1);
    cudaGetSymbolAddress((void**)&p_x2, g_x2);
    cudaGetSymbolAddress((void**)&p_x4, g_x4);
    cudaGetSymbolAddress((void**)&p_xt, g_xt);
    cudaGetSymbolAddress((void**)&p_ya, g_ya);
    cudaGetSymbolAddress((void**)&p_y1, g_y1);
    cudaGetSymbolAddress((void**)&p_y2, g_y2);
    cudaGetSymbolAddress((void**)&p_y4, g_y4);
    cudaGetSymbolAddress((void**)&p_t3, g_t3);
    cudaGetSymbolAddress((void**)&p_cnt_g, g_cnt_g);
    cudaGetSymbolAddress((void**)&p_rp_g, g_rowptr_g);
    cudaGetSymbolAddress((void**)&p_bs_g, g_bsum_g);
    cudaGetSymbolAddress((void**)&p_slots_g, g_slots_g);
    cudaGetSymbolAddress((void**)&p_perm_g, g_perm_g);
    cudaGetSymbolAddress((void**)&p_cnt_lg, g_cnt_lg);
    cudaGetSymbolAddress((void**)&p_rp_lg, g_rowptr_lg);
    cudaGetSymbolAddress((void**)&p_bs_lg, g_bsum_lg);
    cudaGetSymbolAddress((void**)&p_slots_lg, g_slots_lg);
    cudaGetSymbolAddress((void**)&p_perm_lg, g_perm_lg);
    cudaGetSymbolAddress((void**)&p_bins, g_bins);
    cudaGetSymbolAddress((void**)&p_stats, g_stats);
    cudaGetSymbolAddress((void**)&p_coef, g_coef);

    float* ox = (float*)d_out;
    float* oy = ox + (size_t)N * 16;

    const int TB = 256;
    int rp_g  = (N + 4095) & ~4095;
    int rp_lg = (E + 4095) & ~4095;
    int nb_g  = rp_g  / 4096;
    int nb_lg = rp_lg / 4096;

    cudaMemsetAsync(p_stats, 0, 64 * sizeof(double));
    cudaMemsetAsync(p_bins, 0, 256 * sizeof(int));

    // ---- node-graph: padded CSR + degree perm ----
    cudaMemsetAsync(p_cnt_g, 0, (size_t)rp_g * 4);
    k_hist<<<cdiv(E, TB), TB>>>(dst_g, p_cnt_g, E);
    k_scan1<<<nb_g, TB>>>(p_cnt_g, p_bs_g);
    k_scan2<<<1, 1024>>>(p_bs_g, nb_g);
    k_scan3<<<nb_g, TB>>>(p_cnt_g, p_bs_g, p_rp_g, rp_g);
    k_permhist<<<cdiv(N, TB), TB>>>(p_cnt_g, p_bins + 0, N);
    k_permscan<<<1, 64>>>(p_bins + 0);
    k_permfill<<<cdiv(N, TB), TB>>>(p_cnt_g, p_bins + 64, p_perm_g, N);
    cudaMemsetAsync(p_slots_g, 0xFF, sizeof(int2) * (size_t)SL_G_CAP);
    cudaMemsetAsync(p_cnt_g, 0, (size_t)rp_g * 4);
    k_fill_g<<<cdiv(E, TB), TB>>>(src_g, dst_g, p_rp_g, p_cnt_g, p_slots_g, E);

    // ---- line-graph: padded CSR + degree perm ----
    cudaMemsetAsync(p_cnt_lg, 0, (size_t)rp_lg * 4);
    k_hist<<<cdiv(EL, TB), TB>>>(dst_lg, p_cnt_lg, EL);
    k_scan1<<<nb_lg, TB>>>(p_cnt_lg, p_bs_lg);
    k_scan2<<<1, 1024>>>(p_bs_lg, nb_lg);
    k_scan3<<<nb_lg, TB>>>(p_cnt_lg, p_bs_lg, p_rp_lg, rp_lg);
    k_permhist<<<cdiv(E, TB), TB>>>(p_cnt_lg, p_bins + 128, E);
    k_permscan<<<1, 64>>>(p_bins + 128);
    k_permfill<<<cdiv(E, TB), TB>>>(p_cnt_lg, p_bins + 192, p_perm_lg, E);
    cudaMemsetAsync(p_slots_lg, 0xFF, sizeof(int) * (size_t)SL_LG_CAP);
    cudaMemsetAsync(p_cnt_lg, 0, (size_t)rp_lg * 4);
    k_fill_lg<<<cdiv(EL, TB), TB>>>(src_lg, dst_lg, p_rp_lg, p_cnt_lg, p_slots_lg, EL);

    // ---- node branch ----
    k_node_pass1<<<cdiv((long)N * 4, TB), TB>>>(x, y, p_rp_g, p_slots_g, p_perm_g, p_x1, p_yx, N);
    k_spmm_csr2<<<cdiv((long)N * 4, TB), TB>>>(p_x1, p_rp_g, p_slots_g, p_perm_g, p_x2, N);
    k_spmm_csr2<<<cdiv((long)N * 4, TB), TB>>>(p_x2, p_rp_g, p_slots_g, p_perm_g, p_xt, N);
    k_spmm_csr2<<<cdiv((long)N * 4, TB), TB>>>(p_xt, p_rp_g, p_slots_g, p_perm_g, p_x4, N);
    k_combine<<<cdiv(N, TB), TB>>>(x, deg_g, p_yx, p_x1, p_x2, p_x4, thW, thB, ox, p_stats, N);
    k_bnprep<<<1, 16>>>(p_stats, bnxw, bnxb, p_coef, (double)N);
    k_bn<<<cdiv((long)N * 4, TB), TB>>>(ox, p_coef, (long)N * 4);

    // ---- line (edge) branch ----
    k_line_pass1<<<cdiv((long)E * 4, TB), TB>>>(y, x, eid, p_rp_lg, p_slots_lg, p_perm_lg, p_y1, p_ya, E);
    k_spmm_csr<<<cdiv((long)E * 4, TB), TB>>>(p_y1, p_rp_lg, p_slots_lg, p_perm_lg, p_y2, E);
    k_spmm_csr<<<cdiv((long)E * 4, TB), TB>>>(p_y2, p_rp_lg, p_slots_lg, p_perm_lg, p_t3, E);
    k_spmm_csr<<<cdiv((long)E * 4, TB), TB>>>(p_t3, p_rp_lg, p_slots_lg, p_perm_lg, p_y4, E);
    k_combine<<<cdiv(E, TB), TB>>>(y, deg_lg, p_ya, p_y1, p_y2, p_y4, gmW, gmB, oy, p_stats + 32, E);
    k_bnprep<<<1, 16>>>(p_stats + 32, bnyw, bnyb, p_coef + 32, (double)E);
    k_bn<<<cdiv((long)E * 4, TB), TB>>>(oy, p_coef + 32, (long)E * 4);
}

// round 10
// speedup vs baseline: 1.2757x; 1.2757x over previous
#include <cuda_runtime.h>

#define NN   100000
#define NE   1600000
#define NEL  6400000
#define EPSV 1e-5

#define RPAD(x) (((x) + 4095) & ~4095)
#define RP_G  RPAD(NN)
#define RP_LG RPAD(NE)

// padded slot capacities (each row padded to multiple of 4 => +3 max per row)
#define SL_G_CAP  (NE  + 3 * RP_G)
#define SL_LG_CAP (NEL + 3 * RP_LG)

// ---------------- scratch (device globals; no allocation allowed) ----------
__device__ float  g_yx[(size_t)NN * 16];
__device__ float  g_x1[(size_t)NN * 16];
__device__ float  g_x2[(size_t)NN * 16];
__device__ float  g_x4[(size_t)NN * 16];
__device__ float  g_xt[(size_t)NN * 16];
__device__ float  g_ya[(size_t)NE * 16];
__device__ float  g_y1[(size_t)NE * 16];
__device__ float  g_y2[(size_t)NE * 16];
__device__ float  g_y4[(size_t)NE * 16];
__device__ float  g_t3[(size_t)NE * 16];
__device__ int    g_cnt_g[RP_G];
__device__ int    g_rowptr_g[RP_G + 1];     // padded CSR (row len multiple of 4)
__device__ int2   g_slots_g[SL_G_CAP];      // {src, edge_id}, -1 = padding
__device__ int    g_bsum_g[2048];
__device__ int    g_cnt_lg[RP_LG];
__device__ int    g_rowptr_lg[RP_LG + 1];   // padded CSR
__device__ int    g_slots_lg[SL_LG_CAP];    // src, -1 = padding
__device__ int    g_slots_nid[SL_LG_CAP];   // eid2nid[src], -1 = padding
__device__ int    g_bsum_lg[2048];
__device__ double g_stats[64];
__device__ float  g_coef[64];

// ---------------- CSR build kernels ---------------------------------------

__global__ void __launch_bounds__(256) k_hist(
    const int* __restrict__ dst, int* __restrict__ cnt, int nE)
{
    long t = (long)blockIdx.x * 256 + threadIdx.x;
    if (t >= nE) return;
    atomicAdd(&cnt[__ldg(dst + t)], 1);
}

#define PAD4(v) (((v) + 3) & ~3)

// per-block sum of PADDED counts over 4096 rows
__global__ void __launch_bounds__(256) k_scan1(
    const int* __restrict__ cnt, int* __restrict__ bsum)
{
    __shared__ int sh[256];
    int b = blockIdx.x, tid = threadIdx.x;
    const int4* c4 = reinterpret_cast<const int4*>(cnt);
    long base = (long)b * 1024 + (long)tid * 4;
    int s = 0;
    #pragma unroll
    for (int i = 0; i < 4; i++) {
        int4 v = __ldg(c4 + base + i);
        s += PAD4(v.x) + PAD4(v.y) + PAD4(v.z) + PAD4(v.w);
    }
    sh[tid] = s; __syncthreads();
    for (int off = 128; off > 0; off >>= 1) {
        if (tid < off) sh[tid] += sh[tid + off];
        __syncthreads();
    }
    if (tid == 0) bsum[b] = sh[0];
}

__global__ void __launch_bounds__(1024) k_scan2(int* __restrict__ bsum, int nb)
{
    __shared__ int s[2048];
    int tid = threadIdx.x;
    s[tid]        = (tid        < nb) ? bsum[tid]        : 0;
    s[tid + 1024] = (tid + 1024 < nb) ? bsum[tid + 1024] : 0;
    int off = 1;
    for (int d = 1024; d > 0; d >>= 1) {
        __syncthreads();
        if (tid < d) {
            int ai = off * (2 * tid + 1) - 1;
            int bi = off * (2 * tid + 2) - 1;
            s[bi] += s[ai];
        }
        off <<= 1;
    }
    if (tid == 0) s[2047] = 0;
    for (int d = 1; d < 2048; d <<= 1) {
        off >>= 1;
        __syncthreads();
        if (tid < d) {
            int ai = off * (2 * tid + 1) - 1;
            int bi = off * (2 * tid + 2) - 1;
            int t = s[ai]; s[ai] = s[bi]; s[bi] += t;
        }
    }
    __syncthreads();
    if (tid        < nb) bsum[tid]        = s[tid];
    if (tid + 1024 < nb) bsum[tid + 1024] = s[tid + 1024];
}

// final exclusive scan of PADDED counts -> rowptr
__global__ void __launch_bounds__(256) k_scan3(
    const int* __restrict__ cnt, const int* __restrict__ bsum,
    int* __restrict__ rowptr, int RP)
{
    __shared__ int sh[256];
    int b = blockIdx.x, tid = threadIdx.x;
    const int4* c4 = reinterpret_cast<const int4*>(cnt);
    long base4 = (long)b * 1024 + (long)tid * 4;
    int vals[16];
    int tsum = 0;
    #pragma unroll
    for (int i = 0; i < 4; i++) {
        int4 v = __ldg(c4 + base4 + i);
        vals[i * 4 + 0] = PAD4(v.x); vals[i * 4 + 1] = PAD4(v.y);
        vals[i * 4 + 2] = PAD4(v.z); vals[i * 4 + 3] = PAD4(v.w);
        tsum += vals[i*4+0] + vals[i*4+1] + vals[i*4+2] + vals[i*4+3];
    }
    sh[tid] = tsum; __syncthreads();
    for (int off = 1; off < 256; off <<= 1) {
        int t2 = (tid >= off) ? sh[tid - off] : 0;
        __syncthreads();
        sh[tid] += t2;
        __syncthreads();
    }
    int run = __ldg(bsum + b) + sh[tid] - tsum;
    long base = (long)b * 4096 + (long)tid * 16;
    #pragma unroll
    for (int i = 0; i < 16; i++) { rowptr[base + i] = run; run += vals[i]; }
    if (b == gridDim.x - 1 && tid == 255) rowptr[RP] = run;
}

// write sentinel -1 into the <=3 padding slots of each row (cnt = true degree)
__global__ void __launch_bounds__(256) k_pad_g(
    const int* __restrict__ cnt, const int* __restrict__ rowptr,
    int2* __restrict__ slots, int R)
{
    long t = (long)blockIdx.x * 256 + threadIdx.x;
    if (t >= R) return;
    int p   = __ldg(rowptr + t) + __ldg(cnt + t);
    int end = __ldg(rowptr + t + 1);
    for (; p < end; p++) slots[p] = make_int2(-1, -1);
}

__global__ void __launch_bounds__(256) k_pad_lg(
    const int* __restrict__ cnt, const int* __restrict__ rowptr,
    int* __restrict__ slots, int* __restrict__ slots_nid, int R)
{
    long t = (long)blockIdx.x * 256 + threadIdx.x;
    if (t >= R) return;
    int p   = __ldg(rowptr + t) + __ldg(cnt + t);
    int end = __ldg(rowptr + t + 1);
    for (; p < end; p++) { slots[p] = -1; slots_nid[p] = -1; }
}

__global__ void __launch_bounds__(256) k_fill_lg(
    const int* __restrict__ src, const int* __restrict__ dst,
    const int* __restrict__ eid2nid,
    const int* __restrict__ rowptr, int* __restrict__ cnt,
    int* __restrict__ slots, int* __restrict__ slots_nid, int nE)
{
    long t = (long)blockIdx.x * 256 + threadIdx.x;
    if (t >= nE) return;
    int s = __ldg(src + t);
    int d = __ldg(dst + t);
    int p = __ldg(rowptr + d) + atomicAdd(&cnt[d], 1);
    slots[p] = s;
    slots_nid[p] = __ldg(eid2nid + s);
}

__global__ void __launch_bounds__(256) k_fill_g(
    const int* __restrict__ src, const int* __restrict__ dst,
    const int* __restrict__ rowptr, int* __restrict__ cnt,
    int2* __restrict__ slots, int nE)
{
    long t = (long)blockIdx.x * 256 + threadIdx.x;
    if (t >= nE) return;
    int d = __ldg(dst + t);
    int p = __ldg(rowptr + d) + atomicAdd(&cnt[d], 1);
    slots[p] = make_int2(__ldg(src + t), (int)t);
}

// ---------------- SpMM (pull mode, padded CSR, natural order) --------------

#define F4(p) reinterpret_cast<const float4*>(p)

__device__ __forceinline__ void acc4(float4& a, float4 v) {
    a.x += v.x; a.y += v.y; a.z += v.z; a.w += v.w;
}

// out[r] = sum z[slots[e]] ; int slots, padded, sentinel -1.
// TWO rows per thread-quad -> 8 outstanding gathers.
__global__ void __launch_bounds__(256) k_spmm_csr(
    const float* __restrict__ z, const int* __restrict__ rowptr,
    const int* __restrict__ slots, float* __restrict__ out, int R)
{
    long t = (long)blockIdx.x * 256 + threadIdx.x;
    int q = (int)(t >> 2);
    int c = (int)(t & 3);
    int r0 = q << 1;
    if (r0 >= R) return;
    int r1 = r0 + 1;
    bool has1 = (r1 < R);
    int e0   = __ldg(rowptr + r0);
    int end0 = __ldg(rowptr + r0 + 1);
    int e1   = end0;
    int end1 = has1 ? __ldg(rowptr + r1 + 1) : end0;
    const int4* sl4 = reinterpret_cast<const int4*>(slots);
    float4 a0 = make_float4(0.f, 0.f, 0.f, 0.f);
    float4 a1 = make_float4(0.f, 0.f, 0.f, 0.f);
    while (e0 < end0 || e1 < end1) {
        bool d0 = e0 < end0, d1 = e1 < end1;
        int4 s0 = d0 ? __ldg(sl4 + (e0 >> 2)) : make_int4(-1, -1, -1, -1);
        int4 s1 = d1 ? __ldg(sl4 + (e1 >> 2)) : make_int4(-1, -1, -1, -1);
        float4 v00 = __ldg(F4(z) + (((size_t)max(s0.x, 0) << 2) + c));
        float4 v01 = __ldg(F4(z) + (((size_t)max(s0.y, 0) << 2) + c));
        float4 v02 = __ldg(F4(z) + (((size_t)max(s0.z, 0) << 2) + c));
        float4 v03 = __ldg(F4(z) + (((size_t)max(s0.w, 0) << 2) + c));
        float4 v10 = __ldg(F4(z) + (((size_t)max(s1.x, 0) << 2) + c));
        float4 v11 = __ldg(F4(z) + (((size_t)max(s1.y, 0) << 2) + c));
        float4 v12 = __ldg(F4(z) + (((size_t)max(s1.z, 0) << 2) + c));
        float4 v13 = __ldg(F4(z) + (((size_t)max(s1.w, 0) << 2) + c));
        if (s0.x >= 0) acc4(a0, v00);
        if (s0.y >= 0) acc4(a0, v01);
        if (s0.z >= 0) acc4(a0, v02);
        if (s0.w >= 0) acc4(a0, v03);
        if (s1.x >= 0) acc4(a1, v10);
        if (s1.y >= 0) acc4(a1, v11);
        if (s1.z >= 0) acc4(a1, v12);
        if (s1.w >= 0) acc4(a1, v13);
        if (d0) e0 += 4;
        if (d1) e1 += 4;
    }
    reinterpret_cast<float4*>(out)[((size_t)r0 << 2) + c] = a0;
    if (has1) reinterpret_cast<float4*>(out)[((size_t)r1 << 2) + c] = a1;
}

// out[r] = sum z[slots[e].x] ; int2 slots, padded, sentinel {-1,-1}.
// TWO rows per thread-quad.
__global__ void __launch_bounds__(256) k_spmm_csr2(
    const float* __restrict__ z, const int* __restrict__ rowptr,
    const int2* __restrict__ slots, float* __restrict__ out, int R)
{
    long t = (long)blockIdx.x * 256 + threadIdx.x;
    int q = (int)(t >> 2);
    int c = (int)(t & 3);
    int r0 = q << 1;
    if (r0 >= R) return;
    int r1 = r0 + 1;
    bool has1 = (r1 < R);
    int e0   = __ldg(rowptr + r0);
    int end0 = __ldg(rowptr + r0 + 1);
    int e1   = end0;
    int end1 = has1 ? __ldg(rowptr + r1 + 1) : end0;
    const int4* sl4 = reinterpret_cast<const int4*>(slots);  // 2 int2 per int4
    float4 a0 = make_float4(0.f, 0.f, 0.f, 0.f);
    float4 a1 = make_float4(0.f, 0.f, 0.f, 0.f);
    while (e0 < end0 || e1 < end1) {
        bool d0 = e0 < end0, d1 = e1 < end1;
        int4 sa = d0 ? __ldg(sl4 + (e0 >> 1))     : make_int4(-1, -1, -1, -1);
        int4 sb = d0 ? __ldg(sl4 + (e0 >> 1) + 1) : make_int4(-1, -1, -1, -1);
        int4 sc_ = d1 ? __ldg(sl4 + (e1 >> 1))     : make_int4(-1, -1, -1, -1);
        int4 sd = d1 ? __ldg(sl4 + (e1 >> 1) + 1) : make_int4(-1, -1, -1, -1);
        float4 v00 = __ldg(F4(z) + (((size_t)max(sa.x, 0) << 2) + c));
        float4 v01 = __ldg(F4(z) + (((size_t)max(sa.z, 0) << 2) + c));
        float4 v02 = __ldg(F4(z) + (((size_t)max(sb.x, 0) << 2) + c));
        float4 v03 = __ldg(F4(z) + (((size_t)max(sb.z, 0) << 2) + c));
        float4 v10 = __ldg(F4(z) + (((size_t)max(sc_.x, 0) << 2) + c));
        float4 v11 = __ldg(F4(z) + (((size_t)max(sc_.z, 0) << 2) + c));
        float4 v12 = __ldg(F4(z) + (((size_t)max(sd.x, 0) << 2) + c));
        float4 v13 = __ldg(F4(z) + (((size_t)max(sd.z, 0) << 2) + c));
        if (sa.x >= 0) acc4(a0, v00);
        if (sa.z >= 0) acc4(a0, v01);
        if (sb.x >= 0) acc4(a0, v02);
        if (sb.z >= 0) acc4(a0, v03);
        if (sc_.x >= 0) acc4(a1, v10);
        if (sc_.z >= 0) acc4(a1, v11);
        if (sd.x >= 0) acc4(a1, v12);
        if (sd.z >= 0) acc4(a1, v13);
        if (d0) e0 += 4;
        if (d1) e1 += 4;
    }
    reinterpret_cast<float4*>(out)[((size_t)r0 << 2) + c] = a0;
    if (has1) reinterpret_cast<float4*>(out)[((size_t)r1 << 2) + c] = a1;
}

// node pass1: x1[r] = sum x[src], yx[r] = sum y[eid]  (1 row/quad; 8 gathers/iter)
__global__ void __launch_bounds__(256) k_node_pass1(
    const float* __restrict__ x, const float* __restrict__ y,
    const int* __restrict__ rowptr, const int2* __restrict__ slots,
    float* __restrict__ outx1, float* __restrict__ outyx, int R)
{
    long t = (long)blockIdx.x * 256 + threadIdx.x;
    int r = (int)(t >> 2);
    if (r >= R) return;
    int c = (int)(t & 3);
    int e   = __ldg(rowptr + r);
    int end = __ldg(rowptr + r + 1);
    const int4* sl4 = reinterpret_cast<const int4*>(slots);
    float4 ax = make_float4(0.f, 0.f, 0.f, 0.f);
    float4 ay = make_float4(0.f, 0.f, 0.f, 0.f);
    for (; e < end; e += 4) {
        int4 a = __ldg(sl4 + (e >> 1));
        int4 b = __ldg(sl4 + (e >> 1) + 1);
        float4 vx0 = __ldg(F4(x) + (((size_t)max(a.x, 0) << 2) + c));
        float4 vy0 = __ldg(F4(y) + (((size_t)max(a.y, 0) << 2) + c));
        float4 vx1 = __ldg(F4(x) + (((size_t)max(a.z, 0) << 2) + c));
        float4 vy1 = __ldg(F4(y) + (((size_t)max(a.w, 0) << 2) + c));
        float4 vx2 = __ldg(F4(x) + (((size_t)max(b.x, 0) << 2) + c));
        float4 vy2 = __ldg(F4(y) + (((size_t)max(b.y, 0) << 2) + c));
        float4 vx3 = __ldg(F4(x) + (((size_t)max(b.z, 0) << 2) + c));
        float4 vy3 = __ldg(F4(y) + (((size_t)max(b.w, 0) << 2) + c));
        if (a.x >= 0) { acc4(ax, vx0); acc4(ay, vy0); }
        if (a.z >= 0) { acc4(ax, vx1); acc4(ay, vy1); }
        if (b.x >= 0) { acc4(ax, vx2); acc4(ay, vy2); }
        if (b.z >= 0) { acc4(ax, vx3); acc4(ay, vy3); }
    }
    reinterpret_cast<float4*>(outx1)[((size_t)r << 2) + c] = ax;
    reinterpret_cast<float4*>(outyx)[((size_t)r << 2) + c] = ay;
}

// line pass1: y1[r] = sum y[s], ya[r] = sum x[nid[e]]  (precomputed nid; 8 gathers/iter)
__global__ void __launch_bounds__(256) k_line_pass1(
    const float* __restrict__ y, const float* __restrict__ x,
    const int* __restrict__ rowptr, const int* __restrict__ slots,
    const int* __restrict__ slots_nid,
    float* __restrict__ outy1, float* __restrict__ outya, int R)
{
    long t = (long)blockIdx.x * 256 + threadIdx.x;
    int r = (int)(t >> 2);
    if (r >= R) return;
    int c = (int)(t & 3);
    int e   = __ldg(rowptr + r);
    int end = __ldg(rowptr + r + 1);
    const int4* sl4 = reinterpret_cast<const int4*>(slots);
    const int4* sn4 = reinterpret_cast<const int4*>(slots_nid);
    float4 ay  = make_float4(0.f, 0.f, 0.f, 0.f);
    float4 axy = make_float4(0.f, 0.f, 0.f, 0.f);
    for (; e < end; e += 4) {
        int4 s = __ldg(sl4 + (e >> 2));
        int4 n = __ldg(sn4 + (e >> 2));
        float4 vy0 = __ldg(F4(y) + (((size_t)max(s.x, 0) << 2) + c));
        float4 vy1 = __ldg(F4(y) + (((size_t)max(s.y, 0) << 2) + c));
        float4 vy2 = __ldg(F4(y) + (((size_t)max(s.z, 0) << 2) + c));
        float4 vy3 = __ldg(F4(y) + (((size_t)max(s.w, 0) << 2) + c));
        float4 vx0 = __ldg(F4(x) + (((size_t)max(n.x, 0) << 2) + c));
        float4 vx1 = __ldg(F4(x) + (((size_t)max(n.y, 0) << 2) + c));
        float4 vx2 = __ldg(F4(x) + (((size_t)max(n.z, 0) << 2) + c));
        float4 vx3 = __ldg(F4(x) + (((size_t)max(n.w, 0) << 2) + c));
        if (s.x >= 0) { acc4(ay, vy0); acc4(axy, vx0); }
        if (s.y >= 0) { acc4(ay, vy1); acc4(axy, vx1); }
        if (s.z >= 0) { acc4(ay, vy2); acc4(axy, vx2); }
        if (s.w >= 0) { acc4(ay, vy3); acc4(axy, vx3); }
    }
    reinterpret_cast<float4*>(outy1)[((size_t)r << 2) + c] = ay;
    reinterpret_cast<float4*>(outya)[((size_t)r << 2) + c] = axy;
}

// ---------------- combine + BN ---------------------------------------------

__global__ void __launch_bounds__(256) k_combine(
    const float* __restrict__ z0, const float* __restrict__ deg,
    const float* __restrict__ t2p, const float* __restrict__ t3p,
    const float* __restrict__ t4p, const float* __restrict__ t5p,
    const float* __restrict__ W, const float* __restrict__ B,
    float* __restrict__ out, double* __restrict__ stats, int n)
{
    __shared__ float4 sW[768];
    __shared__ float  sB[32];
    __shared__ float  sRed[32];
    int tid = threadIdx.x;
    const float4* W4 = reinterpret_cast<const float4*>(W);
    for (int i = tid; i < 768; i += 256) sW[i] = W4[i];
    if (tid < 32) {
        float b = 0.f;
        #pragma unroll
        for (int t = 0; t < 6; t++) b += B[t * 32 + tid];
        sB[tid] = b;
        sRed[tid] = 0.f;
    }
    __syncthreads();

    long r = (long)blockIdx.x * 256 + tid;
    if (r < (long)n) {
        float acc[32];
        #pragma unroll
        for (int j = 0; j < 32; j++) acc[j] = sB[j];
        float dg = __ldg(deg + r);
        #pragma unroll
        for (int t = 0; t < 6; t++) {
            const float* zp = (t <= 1) ? z0 : (t == 2 ? t2p : (t == 3 ? t3p : (t == 4 ? t4p : t5p)));
            const float4* z4p = F4(zp) + ((size_t)r << 2);
            float4 a0 = __ldg(z4p + 0);
            float4 a1 = __ldg(z4p + 1);
            float4 a2 = __ldg(z4p + 2);
            float4 a3 = __ldg(z4p + 3);
            if (t == 1) {
                a0.x *= dg; a0.y *= dg; a0.z *= dg; a0.w *= dg;
                a1.x *= dg; a1.y *= dg; a1.z *= dg; a1.w *= dg;
                a2.x *= dg; a2.y *= dg; a2.z *= dg; a2.w *= dg;
                a3.x *= dg; a3.y *= dg; a3.z *= dg; a3.w *= dg;
            }
            #pragma unroll
            for (int j = 0; j < 32; j++) {
                const float4* w = &sW[(t * 32 + j) * 4];
                float4 w0 = w[0], w1 = w[1], w2 = w[2], w3 = w[3];
                float s = acc[j];
                s += a0.x * w0.x + a0.y * w0.y + a0.z * w0.z + a0.w * w0.w;
                s += a1.x * w1.x + a1.y * w1.y + a1.z * w1.z + a1.w * w1.w;
                s += a2.x * w2.x + a2.y * w2.y + a2.z * w2.z + a2.w * w2.w;
                s += a3.x * w3.x + a3.y * w3.y + a3.z * w3.z + a3.w * w3.w;
                acc[j] = s;
            }
        }
        float h[16];
        #pragma unroll
        for (int j = 0; j < 16; j++) h[j] = acc[j] + fmaxf(acc[j + 16], 0.f);
        float4* o = reinterpret_cast<float4*>(out) + ((size_t)r << 2);
        o[0] = make_float4(h[0], h[1], h[2], h[3]);
        o[1] = make_float4(h[4], h[5], h[6], h[7]);
        o[2] = make_float4(h[8], h[9], h[10], h[11]);
        o[3] = make_float4(h[12], h[13], h[14], h[15]);
        #pragma unroll
        for (int c = 0; c < 16; c++) {
            atomicAdd(&sRed[c], h[c]);
            atomicAdd(&sRed[16 + c], h[c] * h[c]);
        }
    }
    __syncthreads();
    if (tid < 32) atomicAdd(&stats[tid], (double)sRed[tid]);
}

__global__ void k_bnprep(const double* __restrict__ stats, const float* __restrict__ w,
                         const float* __restrict__ b, float* __restrict__ coef, double n)
{
    int c = threadIdx.x;
    if (c >= 16) return;
    double m   = stats[c] / n;
    double var = stats[16 + c] / n - m * m;
    double s   = (double)w[c] / sqrt(var + (double)EPSV);
    coef[c]      = (float)s;
    coef[16 + c] = (float)((double)b[c] - m * s);
}

__global__ void __launch_bounds__(256) k_bn(
    float* __restrict__ h, const float* __restrict__ coef, long n4)
{
    long t = (long)blockIdx.x * 256 + threadIdx.x;
    if (t >= n4) return;
    int c = (int)(t & 3);
    float4 sc = reinterpret_cast<const float4*>(coef)[c];
    float4 sh = reinterpret_cast<const float4*>(coef)[4 + c];
    float4 v = reinterpret_cast<float4*>(h)[t];
    v.x = v.x * sc.x + sh.x;
    v.y = v.y * sc.y + sh.y;
    v.z = v.z * sc.z + sh.z;
    v.w = v.w * sc.w + sh.w;
    reinterpret_cast<float4*>(h)[t] = v;
}

// ---------------- host -----------------------------------------------------

static inline int cdiv(long a, int b) { return (int)((a + (long)b - 1) / b); }

extern "C" void kernel_launch(void* const* d_in, const int* in_sizes, int n_in,
                              void* d_out, int out_size)
{
    const float* x      = (const float*)d_in[0];
    const float* y      = (const float*)d_in[1];
    const float* deg_g  = (const float*)d_in[2];
    const float* deg_lg = (const float*)d_in[3];
    const float* thW    = (const float*)d_in[4];
    const float* thB    = (const float*)d_in[5];
    const float* gmW    = (const float*)d_in[6];
    const float* gmB    = (const float*)d_in[7];
    const float* bnxw   = (const float*)d_in[8];
    const float* bnxb   = (const float*)d_in[9];
    const float* bnyw   = (const float*)d_in[10];
    const float* bnyb   = (const float*)d_in[11];
    const int* src_g    = (const int*)d_in[12];
    const int* dst_g    = (const int*)d_in[13];
    const int* src_lg   = (const int*)d_in[14];
    const int* dst_lg   = (const int*)d_in[15];
    const int* eid      = (const int*)d_in[16];

    int N  = in_sizes[2];
    int E  = in_sizes[3];
    int EL = in_sizes[14];

    float *p_yx, *p_x1, *p_x2, *p_x4, *p_xt;
    float *p_ya, *p_y1, *p_y2, *p_y4, *p_t3, *p_coef;
    int *p_cnt_g, *p_rp_g, *p_bs_g, *p_cnt_lg, *p_rp_lg, *p_bs_lg;
    int *p_slots_lg, *p_slots_nid;
    int2* p_slots_g;
    double* p_stats;
    cudaGetSymbolAddress((void**)&p_yx, g_yx);
    cudaGetSymbolAddress((void**)&p_x1, g_x1);
    cudaGetSymbolAddress((void**)&p_x2, g_x2);
    cudaGetSymbolAddress((void**)&p_x4, g_x4);
    cudaGetSymbolAddress((void**)&p_xt, g_xt);
    cudaGetSymbolAddress((void**)&p_ya, g_ya);
    cudaGetSymbolAddress((void**)&p_y1, g_y1);
    cudaGetSymbolAddress((void**)&p_y2, g_y2);
    cudaGetSymbolAddress((void**)&p_y4, g_y4);
    cudaGetSymbolAddress((void**)&p_t3, g_t3);
    cudaGetSymbolAddress((void**)&p_cnt_g, g_cnt_g);
    cudaGetSymbolAddress((void**)&p_rp_g, g_rowptr_g);
    cudaGetSymbolAddress((void**)&p_bs_g, g_bsum_g);
    cudaGetSymbolAddress((void**)&p_slots_g, g_slots_g);
    cudaGetSymbolAddress((void**)&p_cnt_lg, g_cnt_lg);
    cudaGetSymbolAddress((void**)&p_rp_lg, g_rowptr_lg);
    cudaGetSymbolAddress((void**)&p_bs_lg, g_bsum_lg);
    cudaGetSymbolAddress((void**)&p_slots_lg, g_slots_lg);
    cudaGetSymbolAddress((void**)&p_slots_nid, g_slots_nid);
    cudaGetSymbolAddress((void**)&p_stats, g_stats);
    cudaGetSymbolAddress((void**)&p_coef, g_coef);

    float* ox = (float*)d_out;
    float* oy = ox + (size_t)N * 16;

    const int TB = 256;
    int rp_g  = (N + 4095) & ~4095;
    int rp_lg = (E + 4095) & ~4095;
    int nb_g  = rp_g  / 4096;
    int nb_lg = rp_lg / 4096;

    cudaMemsetAsync(p_stats, 0, 64 * sizeof(double));

    // ---- node-graph: padded CSR ----
    cudaMemsetAsync(p_cnt_g, 0, (size_t)rp_g * 4);
    k_hist<<<cdiv(E, TB), TB>>>(dst_g, p_cnt_g, E);
    k_scan1<<<nb_g, TB>>>(p_cnt_g, p_bs_g);
    k_scan2<<<1, 1024>>>(p_bs_g, nb_g);
    k_scan3<<<nb_g, TB>>>(p_cnt_g, p_bs_g, p_rp_g, rp_g);
    k_pad_g<<<cdiv(N, TB), TB>>>(p_cnt_g, p_rp_g, p_slots_g, N);
    cudaMemsetAsync(p_cnt_g, 0, (size_t)rp_g * 4);
    k_fill_g<<<cdiv(E, TB), TB>>>(src_g, dst_g, p_rp_g, p_cnt_g, p_slots_g, E);

    // ---- line-graph: padded CSR + precomputed nid ----
    cudaMemsetAsync(p_cnt_lg, 0, (size_t)rp_lg * 4);
    k_hist<<<cdiv(EL, TB), TB>>>(dst_lg, p_cnt_lg, EL);
    k_scan1<<<nb_lg, TB>>>(p_cnt_lg, p_bs_lg);
    k_scan2<<<1, 1024>>>(p_bs_lg, nb_lg);
    k_scan3<<<nb_lg, TB>>>(p_cnt_lg, p_bs_lg, p_rp_lg, rp_lg);
    k_pad_lg<<<cdiv(E, TB), TB>>>(p_cnt_lg, p_rp_lg, p_slots_lg, p_slots_nid, E);
    cudaMemsetAsync(p_cnt_lg, 0, (size_t)rp_lg * 4);
    k_fill_lg<<<cdiv(EL, TB), TB>>>(src_lg, dst_lg, eid, p_rp_lg, p_cnt_lg,
                                    p_slots_lg, p_slots_nid, EL);

    // ---- node branch ----
    k_node_pass1<<<cdiv((long)N * 4, TB), TB>>>(x, y, p_rp_g, p_slots_g, p_x1, p_yx, N);
    {
        long q4 = ((long)(N + 1) / 2) * 4;
        k_spmm_csr2<<<cdiv(q4, TB), TB>>>(p_x1, p_rp_g, p_slots_g, p_x2, N);
        k_spmm_csr2<<<cdiv(q4, TB), TB>>>(p_x2, p_rp_g, p_slots_g, p_xt, N);
        k_spmm_csr2<<<cdiv(q4, TB), TB>>>(p_xt, p_rp_g, p_slots_g, p_x4, N);
    }
    k_combine<<<cdiv(N, TB), TB>>>(x, deg_g, p_yx, p_x1, p_x2, p_x4, thW, thB, ox, p_stats, N);
    k_bnprep<<<1, 16>>>(p_stats, bnxw, bnxb, p_coef, (double)N);
    k_bn<<<cdiv((long)N * 4, TB), TB>>>(ox, p_coef, (long)N * 4);

    // ---- line (edge) branch ----
    k_line_pass1<<<cdiv((long)E * 4, TB), TB>>>(y, x, p_rp_lg, p_slots_lg, p_slots_nid,
                                                p_y1, p_ya, E);
    {
        long q4 = ((long)(E + 1) / 2) * 4;
        k_spmm_csr<<<cdiv(q4, TB), TB>>>(p_y1, p_rp_lg, p_slots_lg, p_y2, E);
        k_spmm_csr<<<cdiv(q4, TB), TB>>>(p_y2, p_rp_lg, p_slots_lg, p_t3, E);
        k_spmm_csr<<<cdiv(q4, TB), TB>>>(p_t3, p_rp_lg, p_slots_lg, p_y4, E);
    }
    k_combine<<<cdiv(E, TB), TB>>>(y, deg_lg, p_ya, p_y1, p_y2, p_y4, gmW, gmB, oy, p_stats + 32, E);
    k_bnprep<<<1, 16>>>(p_stats + 32, bnyw, bnyb, p_coef + 32, (double)E);
    k_bn<<<cdiv((long)E * 4, TB), TB>>>(oy, p_coef + 32, (long)E * 4);
}

// round 12
// speedup vs baseline: 1.2830x; 1.0058x over previous
#include <cuda_runtime.h>
#include <cuda_fp16.h>

#define NN   100000
#define NE   1600000
#define NEL  6400000
#define EPSV 1e-5

#define RPAD(x) (((x) + 4095) & ~4095)
#define RP_G  RPAD(NN)
#define RP_LG RPAD(NE)

// padded slot capacities (each row padded to multiple of 4 => +3 max per row)
#define SL_G_CAP  (NE  + 3 * RP_G)
#define SL_LG_CAP (NEL + 3 * RP_LG)

// ---------------- scratch (device globals; no allocation allowed) ----------
__device__ float  g_yx[(size_t)NN * 16];
__device__ float  g_x1[(size_t)NN * 16];
__device__ float  g_x2[(size_t)NN * 16];
__device__ float  g_x4[(size_t)NN * 16];
__device__ float  g_xt[(size_t)NN * 16];
__device__ float  g_ya[(size_t)NE * 16];
__device__ float  g_y1[(size_t)NE * 16];
__device__ float  g_y2[(size_t)NE * 16];
__device__ float  g_y4[(size_t)NE * 16];
__device__ __half g_y1h[(size_t)NE * 16];   // fp16 copies for L2-resident gathers
__device__ __half g_y2h[(size_t)NE * 16];
__device__ __half g_t3h[(size_t)NE * 16];
__device__ int    g_cnt_g[RP_G];
__device__ int    g_rowptr_g[RP_G + 1];     // padded CSR (row len multiple of 4)
__device__ int2   g_slots_g[SL_G_CAP];      // {src, edge_id}, -1 = padding
__device__ int    g_bsum_g[2048];
__device__ int    g_cnt_lg[RP_LG];
__device__ int    g_rowptr_lg[RP_LG + 1];   // padded CSR
__device__ int    g_slots_lg[SL_LG_CAP];    // src, -1 = padding
__device__ int    g_slots_nid[SL_LG_CAP];   // eid2nid[src], -1 = padding
__device__ int    g_bsum_lg[2048];
__device__ double g_stats[64];
__device__ float  g_coef[64];

// ---------------- CSR build kernels ---------------------------------------

__global__ void __launch_bounds__(256) k_hist(
    const int* __restrict__ dst, int* __restrict__ cnt, int nE)
{
    long t = (long)blockIdx.x * 256 + threadIdx.x;
    if (t >= nE) return;
    atomicAdd(&cnt[__ldg(dst + t)], 1);
}

#define PAD4(v) (((v) + 3) & ~3)

// per-block sum of PADDED counts over 4096 rows
__global__ void __launch_bounds__(256) k_scan1(
    const int* __restrict__ cnt, int* __restrict__ bsum)
{
    __shared__ int sh[256];
    int b = blockIdx.x, tid = threadIdx.x;
    const int4* c4 = reinterpret_cast<const int4*>(cnt);
    long base = (long)b * 1024 + (long)tid * 4;
    int s = 0;
    #pragma unroll
    for (int i = 0; i < 4; i++) {
        int4 v = __ldg(c4 + base + i);
        s += PAD4(v.x) + PAD4(v.y) + PAD4(v.z) + PAD4(v.w);
    }
    sh[tid] = s; __syncthreads();
    for (int off = 128; off > 0; off >>= 1) {
        if (tid < off) sh[tid] += sh[tid + off];
        __syncthreads();
    }
    if (tid == 0) bsum[b] = sh[0];
}

__global__ void __launch_bounds__(1024) k_scan2(int* __restrict__ bsum, int nb)
{
    __shared__ int s[2048];
    int tid = threadIdx.x;
    s[tid]        = (tid        < nb) ? bsum[tid]        : 0;
    s[tid + 1024] = (tid + 1024 < nb) ? bsum[tid + 1024] : 0;
    int off = 1;
    for (int d = 1024; d > 0; d >>= 1) {
        __syncthreads();
        if (tid < d) {
            int ai = off * (2 * tid + 1) - 1;
            int bi = off * (2 * tid + 2) - 1;
            s[bi] += s[ai];
        }
        off <<= 1;
    }
    if (tid == 0) s[2047] = 0;
    for (int d = 1; d < 2048; d <<= 1) {
        off >>= 1;
        __syncthreads();
        if (tid < d) {
            int ai = off * (2 * tid + 1) - 1;
            int bi = off * (2 * tid + 2) - 1;
            int t = s[ai]; s[ai] = s[bi]; s[bi] += t;
        }
    }
    __syncthreads();
    if (tid        < nb) bsum[tid]        = s[tid];
    if (tid + 1024 < nb) bsum[tid + 1024] = s[tid + 1024];
}

// final exclusive scan of PADDED counts -> rowptr
__global__ void __launch_bounds__(256) k_scan3(
    const int* __restrict__ cnt, const int* __restrict__ bsum,
    int* __restrict__ rowptr, int RP)
{
    __shared__ int sh[256];
    int b = blockIdx.x, tid = threadIdx.x;
    const int4* c4 = reinterpret_cast<const int4*>(cnt);
    long base4 = (long)b * 1024 + (long)tid * 4;
    int vals[16];
    int tsum = 0;
    #pragma unroll
    for (int i = 0; i < 4; i++) {
        int4 v = __ldg(c4 + base4 + i);
        vals[i * 4 + 0] = PAD4(v.x); vals[i * 4 + 1] = PAD4(v.y);
        vals[i * 4 + 2] = PAD4(v.z); vals[i * 4 + 3] = PAD4(v.w);
        tsum += vals[i*4+0] + vals[i*4+1] + vals[i*4+2] + vals[i*4+3];
    }
    sh[tid] = tsum; __syncthreads();
    for (int off = 1; off < 256; off <<= 1) {
        int t2 = (tid >= off) ? sh[tid - off] : 0;
        __syncthreads();
        sh[tid] += t2;
        __syncthreads();
    }
    int run = __ldg(bsum + b) + sh[tid] - tsum;
    long base = (long)b * 4096 + (long)tid * 16;
    #pragma unroll
    for (int i = 0; i < 16; i++) { rowptr[base + i] = run; run += vals[i]; }
    if (b == gridDim.x - 1 && tid == 255) rowptr[RP] = run;
}

// write sentinel -1 into the <=3 padding slots of each row (cnt = true degree)
__global__ void __launch_bounds__(256) k_pad_g(
    const int* __restrict__ cnt, const int* __restrict__ rowptr,
    int2* __restrict__ slots, int R)
{
    long t = (long)blockIdx.x * 256 + threadIdx.x;
    if (t >= R) return;
    int p   = __ldg(rowptr + t) + __ldg(cnt + t);
    int end = __ldg(rowptr + t + 1);
    for (; p < end; p++) slots[p] = make_int2(-1, -1);
}

__global__ void __launch_bounds__(256) k_pad_lg(
    const int* __restrict__ cnt, const int* __restrict__ rowptr,
    int* __restrict__ slots, int* __restrict__ slots_nid, int R)
{
    long t = (long)blockIdx.x * 256 + threadIdx.x;
    if (t >= R) return;
    int p   = __ldg(rowptr + t) + __ldg(cnt + t);
    int end = __ldg(rowptr + t + 1);
    for (; p < end; p++) { slots[p] = -1; slots_nid[p] = -1; }
}

__global__ void __launch_bounds__(256) k_fill_lg(
    const int* __restrict__ src, const int* __restrict__ dst,
    const int* __restrict__ eid2nid,
    const int* __restrict__ rowptr, int* __restrict__ cnt,
    int* __restrict__ slots, int* __restrict__ slots_nid, int nE)
{
    long t = (long)blockIdx.x * 256 + threadIdx.x;
    if (t >= nE) return;
    int s = __ldg(src + t);
    int d = __ldg(dst + t);
    int p = __ldg(rowptr + d) + atomicAdd(&cnt[d], 1);
    slots[p] = s;
    slots_nid[p] = __ldg(eid2nid + s);
}

__global__ void __launch_bounds__(256) k_fill_g(
    const int* __restrict__ src, const int* __restrict__ dst,
    const int* __restrict__ rowptr, int* __restrict__ cnt,
    int2* __restrict__ slots, int nE)
{
    long t = (long)blockIdx.x * 256 + threadIdx.x;
    if (t >= nE) return;
    int d = __ldg(dst + t);
    int p = __ldg(rowptr + d) + atomicAdd(&cnt[d], 1);
    slots[p] = make_int2(__ldg(src + t), (int)t);
}

// ---------------- SpMM (pull mode, padded CSR) -----------------------------

#define F4(p) reinterpret_cast<const float4*>(p)

__device__ __forceinline__ void acc4(float4& a, float4 v) {
    a.x += v.x; a.y += v.y; a.z += v.z; a.w += v.w;
}

__device__ __forceinline__ void accH(float* a, uint4 u) {
    const __half2* h = reinterpret_cast<const __half2*>(&u);
    float2 f;
    f = __half22float2(h[0]); a[0] += f.x; a[1] += f.y;
    f = __half22float2(h[1]); a[2] += f.x; a[3] += f.y;
    f = __half22float2(h[2]); a[4] += f.x; a[5] += f.y;
    f = __half22float2(h[3]); a[6] += f.x; a[7] += f.y;
}

// fp16-gather SpMM: 2 threads per row; each thread covers 8 channels (16B).
// Optionally writes fp32 output (for combine) and/or fp16 output (next pass).
__global__ void __launch_bounds__(256) k_spmm_h(
    const __half* __restrict__ zh, const int* __restrict__ rowptr,
    const int* __restrict__ slots, float* __restrict__ out,
    __half* __restrict__ outh, int R)
{
    long t = (long)blockIdx.x * 256 + threadIdx.x;
    int r = (int)(t >> 1);
    if (r >= R) return;
    int hf = (int)(t & 1);
    int e   = __ldg(rowptr + r);
    int end = __ldg(rowptr + r + 1);
    const int4* sl4 = reinterpret_cast<const int4*>(slots);
    const uint4* zp = reinterpret_cast<const uint4*>(zh);
    float a[8];
    #pragma unroll
    for (int j = 0; j < 8; j++) a[j] = 0.f;
    for (; e < end; e += 4) {
        int4 s = __ldcs(sl4 + (e >> 2));
        uint4 u0 = __ldg(zp + (((size_t)max(s.x, 0) << 1) + hf));
        uint4 u1 = __ldg(zp + (((size_t)max(s.y, 0) << 1) + hf));
        uint4 u2 = __ldg(zp + (((size_t)max(s.z, 0) << 1) + hf));
        uint4 u3 = __ldg(zp + (((size_t)max(s.w, 0) << 1) + hf));
        if (s.x >= 0) accH(a, u0);
        if (s.y >= 0) accH(a, u1);
        if (s.z >= 0) accH(a, u2);
        if (s.w >= 0) accH(a, u3);
    }
    if (out) {
        float4* o4 = reinterpret_cast<float4*>(out) + (((size_t)r << 2) + (hf << 1));
        __stcs(o4,     make_float4(a[0], a[1], a[2], a[3]));
        __stcs(o4 + 1, make_float4(a[4], a[5], a[6], a[7]));
    }
    if (outh) {
        __half2 p0 = __floats2half2_rn(a[0], a[1]);
        __half2 p1 = __floats2half2_rn(a[2], a[3]);
        __half2 p2 = __floats2half2_rn(a[4], a[5]);
        __half2 p3 = __floats2half2_rn(a[6], a[7]);
        uint4 u;
        u.x = *reinterpret_cast<unsigned*>(&p0);
        u.y = *reinterpret_cast<unsigned*>(&p1);
        u.z = *reinterpret_cast<unsigned*>(&p2);
        u.w = *reinterpret_cast<unsigned*>(&p3);
        reinterpret_cast<uint4*>(outh)[((size_t)r << 1) + hf] = u;  // keep L2-resident
    }
}

// out[r] = sum z[slots[e].x] ; int2 slots, padded, sentinel {-1,-1}. (node graph)
__global__ void __launch_bounds__(256) k_spmm_csr2(
    const float* __restrict__ z, const int* __restrict__ rowptr,
    const int2* __restrict__ slots, float* __restrict__ out, int R)
{
    long t = (long)blockIdx.x * 256 + threadIdx.x;
    int r = (int)(t >> 2);
    if (r >= R) return;
    int c = (int)(t & 3);
    int e   = __ldg(rowptr + r);
    int end = __ldg(rowptr + r + 1);
    const int4* sl4 = reinterpret_cast<const int4*>(slots);  // 2 int2 per int4
    float4 acc = make_float4(0.f, 0.f, 0.f, 0.f);
    for (; e < end; e += 4) {
        int4 sa = __ldg(sl4 + (e >> 1));
        int4 sb = __ldg(sl4 + (e >> 1) + 1);
        float4 v0 = __ldg(F4(z) + (((size_t)max(sa.x, 0) << 2) + c));
        float4 v1 = __ldg(F4(z) + (((size_t)max(sa.z, 0) << 2) + c));
        float4 v2 = __ldg(F4(z) + (((size_t)max(sb.x, 0) << 2) + c));
        float4 v3 = __ldg(F4(z) + (((size_t)max(sb.z, 0) << 2) + c));
        if (sa.x >= 0) acc4(acc, v0);
        if (sa.z >= 0) acc4(acc, v1);
        if (sb.x >= 0) acc4(acc, v2);
        if (sb.z >= 0) acc4(acc, v3);
    }
    reinterpret_cast<float4*>(out)[((size_t)r << 2) + c] = acc;
}

// node pass1: x1[r] = sum x[src], yx[r] = sum y[eid]
__global__ void __launch_bounds__(256) k_node_pass1(
    const float* __restrict__ x, const float* __restrict__ y,
    const int* __restrict__ rowptr, const int2* __restrict__ slots,
    float* __restrict__ outx1, float* __restrict__ outyx, int R)
{
    long t = (long)blockIdx.x * 256 + threadIdx.x;
    int r = (int)(t >> 2);
    if (r >= R) return;
    int c = (int)(t & 3);
    int e   = __ldg(rowptr + r);
    int end = __ldg(rowptr + r + 1);
    const int4* sl4 = reinterpret_cast<const int4*>(slots);
    float4 ax = make_float4(0.f, 0.f, 0.f, 0.f);
    float4 ay = make_float4(0.f, 0.f, 0.f, 0.f);
    for (; e < end; e += 4) {
        int4 a = __ldg(sl4 + (e >> 1));
        int4 b = __ldg(sl4 + (e >> 1) + 1);
        float4 vx0 = __ldg(F4(x) + (((size_t)max(a.x, 0) << 2) + c));
        float4 vy0 = __ldg(F4(y) + (((size_t)max(a.y, 0) << 2) + c));
        float4 vx1 = __ldg(F4(x) + (((size_t)max(a.z, 0) << 2) + c));
        float4 vy1 = __ldg(F4(y) + (((size_t)max(a.w, 0) << 2) + c));
        float4 vx2 = __ldg(F4(x) + (((size_t)max(b.x, 0) << 2) + c));
        float4 vy2 = __ldg(F4(y) + (((size_t)max(b.y, 0) << 2) + c));
        float4 vx3 = __ldg(F4(x) + (((size_t)max(b.z, 0) << 2) + c));
        float4 vy3 = __ldg(F4(y) + (((size_t)max(b.w, 0) << 2) + c));
        if (a.x >= 0) { acc4(ax, vx0); acc4(ay, vy0); }
        if (a.z >= 0) { acc4(ax, vx1); acc4(ay, vy1); }
        if (b.x >= 0) { acc4(ax, vx2); acc4(ay, vy2); }
        if (b.z >= 0) { acc4(ax, vx3); acc4(ay, vy3); }
    }
    reinterpret_cast<float4*>(outx1)[((size_t)r << 2) + c] = ax;
    reinterpret_cast<float4*>(outyx)[((size_t)r << 2) + c] = ay;
}

// line pass1: y1[r] = sum y[s] (fp32 + fp16 copy), ya[r] = sum x[nid[e]]
__global__ void __launch_bounds__(256) k_line_pass1(
    const float* __restrict__ y, const float* __restrict__ x,
    const int* __restrict__ rowptr, const int* __restrict__ slots,
    const int* __restrict__ slots_nid,
    float* __restrict__ outy1, float* __restrict__ outya,
    __half* __restrict__ outy1h, int R)
{
    long t = (long)blockIdx.x * 256 + threadIdx.x;
    int r = (int)(t >> 2);
    if (r >= R) return;
    int c = (int)(t & 3);
    int e   = __ldg(rowptr + r);
    int end = __ldg(rowptr + r + 1);
    const int4* sl4 = reinterpret_cast<const int4*>(slots);
    const int4* sn4 = reinterpret_cast<const int4*>(slots_nid);
    float4 ay  = make_float4(0.f, 0.f, 0.f, 0.f);
    float4 axy = make_float4(0.f, 0.f, 0.f, 0.f);
    for (; e < end; e += 4) {
        int4 s = __ldcs(sl4 + (e >> 2));
        int4 n = __ldcs(sn4 + (e >> 2));
        float4 vy0 = __ldg(F4(y) + (((size_t)max(s.x, 0) << 2) + c));
        float4 vy1 = __ldg(F4(y) + (((size_t)max(s.y, 0) << 2) + c));
        float4 vy2 = __ldg(F4(y) + (((size_t)max(s.z, 0) << 2) + c));
        float4 vy3 = __ldg(F4(y) + (((size_t)max(s.w, 0) << 2) + c));
        float4 vx0 = __ldg(F4(x) + (((size_t)max(n.x, 0) << 2) + c));
        float4 vx1 = __ldg(F4(x) + (((size_t)max(n.y, 0) << 2) + c));
        float4 vx2 = __ldg(F4(x) + (((size_t)max(n.z, 0) << 2) + c));
        float4 vx3 = __ldg(F4(x) + (((size_t)max(n.w, 0) << 2) + c));
        if (s.x >= 0) { acc4(ay, vy0); acc4(axy, vx0); }
        if (s.y >= 0) { acc4(ay, vy1); acc4(axy, vx1); }
        if (s.z >= 0) { acc4(ay, vy2); acc4(axy, vx2); }
        if (s.w >= 0) { acc4(ay, vy3); acc4(axy, vx3); }
    }
    __stcs(reinterpret_cast<float4*>(outy1) + (((size_t)r << 2) + c), ay);
    __stcs(reinterpret_cast<float4*>(outya) + (((size_t)r << 2) + c), axy);
    __half2 q0 = __floats2half2_rn(ay.x, ay.y);
    __half2 q1 = __floats2half2_rn(ay.z, ay.w);
    uint2 u;
    u.x = *reinterpret_cast<unsigned*>(&q0);
    u.y = *reinterpret_cast<unsigned*>(&q1);
    reinterpret_cast<uint2*>(outy1h)[((size_t)r << 2) + c] = u;  // keep L2-resident
}

// ---------------- combine + BN ---------------------------------------------

__global__ void __launch_bounds__(256) k_combine(
    const float* __restrict__ z0, const float* __restrict__ deg,
    const float* __restrict__ t2p, const float* __restrict__ t3p,
    const float* __restrict__ t4p, const float* __restrict__ t5p,
    const float* __restrict__ W, const float* __restrict__ B,
    float* __restrict__ out, double* __restrict__ stats, int n)
{
    __shared__ float4 sW[768];
    __shared__ float  sB[32];
    __shared__ float  sRed[32];
    int tid = threadIdx.x;
    const float4* W4 = reinterpret_cast<const float4*>(W);
    for (int i = tid; i < 768; i += 256) sW[i] = W4[i];
    if (tid < 32) {
        float b = 0.f;
        #pragma unroll
        for (int t = 0; t < 6; t++) b += B[t * 32 + tid];
        sB[tid] = b;
        sRed[tid] = 0.f;
    }
    __syncthreads();

    long r = (long)blockIdx.x * 256 + tid;
    if (r < (long)n) {
        float acc[32];
        #pragma unroll
        for (int j = 0; j < 32; j++) acc[j] = sB[j];
        float dg = __ldg(deg + r);
        #pragma unroll
        for (int t = 0; t < 6; t++) {
            const float* zp = (t <= 1) ? z0 : (t == 2 ? t2p : (t == 3 ? t3p : (t == 4 ? t4p : t5p)));
            const float4* z4p = F4(zp) + ((size_t)r << 2);
            float4 a0 = __ldg(z4p + 0);
            float4 a1 = __ldg(z4p + 1);
            float4 a2 = __ldg(z4p + 2);
            float4 a3 = __ldg(z4p + 3);
            if (t == 1) {
                a0.x *= dg; a0.y *= dg; a0.z *= dg; a0.w *= dg;
                a1.x *= dg; a1.y *= dg; a1.z *= dg; a1.w *= dg;
                a2.x *= dg; a2.y *= dg; a2.z *= dg; a2.w *= dg;
                a3.x *= dg; a3.y *= dg; a3.z *= dg; a3.w *= dg;
            }
            #pragma unroll
            for (int j = 0; j < 32; j++) {
                const float4* w = &sW[(t * 32 + j) * 4];
                float4 w0 = w[0], w1 = w[1], w2 = w[2], w3 = w[3];
                float s = acc[j];
                s += a0.x * w0.x + a0.y * w0.y + a0.z * w0.z + a0.w * w0.w;
                s += a1.x * w1.x + a1.y * w1.y + a1.z * w1.z + a1.w * w1.w;
                s += a2.x * w2.x + a2.y * w2.y + a2.z * w2.z + a2.w * w2.w;
                s += a3.x * w3.x + a3.y * w3.y + a3.z * w3.z + a3.w * w3.w;
                acc[j] = s;
            }
        }
        float h[16];
        #pragma unroll
        for (int j = 0; j < 16; j++) h[j] = acc[j] + fmaxf(acc[j + 16], 0.f);
        float4* o = reinterpret_cast<float4*>(out) + ((size_t)r << 2);
        o[0] = make_float4(h[0], h[1], h[2], h[3]);
        o[1] = make_float4(h[4], h[5], h[6], h[7]);
        o[2] = make_float4(h[8], h[9], h[10], h[11]);
        o[3] = make_float4(h[12], h[13], h[14], h[15]);
        #pragma unroll
        for (int c = 0; c < 16; c++) {
            atomicAdd(&sRed[c], h[c]);
            atomicAdd(&sRed[16 + c], h[c] * h[c]);
        }
    }
    __syncthreads();
    if (tid < 32) atomicAdd(&stats[tid], (double)sRed[tid]);
}

__global__ void k_bnprep(const double* __restrict__ stats, const float* __restrict__ w,
                         const float* __restrict__ b, float* __restrict__ coef, double n)
{
    int c = threadIdx.x;
    if (c >= 16) return;
    double m   = stats[c] / n;
    double var = stats[16 + c] / n - m * m;
    double s   = (double)w[c] / sqrt(var + (double)EPSV);
    coef[c]      = (float)s;
    coef[16 + c] = (float)((double)b[c] - m * s);
}

__global__ void __launch_bounds__(256) k_bn(
    float* __restrict__ h, const float* __restrict__ coef, long n4)
{
    long t = (long)blockIdx.x * 256 + threadIdx.x;
    if (t >= n4) return;
    int c = (int)(t & 3);
    float4 sc = reinterpret_cast<const float4*>(coef)[c];
    float4 sh = reinterpret_cast<const float4*>(coef)[4 + c];
    float4 v = reinterpret_cast<float4*>(h)[t];
    v.x = v.x * sc.x + sh.x;
    v.y = v.y * sc.y + sh.y;
    v.z = v.z * sc.z + sh.z;
    v.w = v.w * sc.w + sh.w;
    reinterpret_cast<float4*>(h)[t] = v;
}

// ---------------- host -----------------------------------------------------

static inline int cdiv(long a, int b) { return (int)((a + (long)b - 1) / b); }

extern "C" void kernel_launch(void* const* d_in, const int* in_sizes, int n_in,
                              void* d_out, int out_size)
{
    const float* x      = (const float*)d_in[0];
    const float* y      = (const float*)d_in[1];
    const float* deg_g  = (const float*)d_in[2];
    const float* deg_lg = (const float*)d_in[3];
    const float* thW    = (const float*)d_in[4];
    const float* thB    = (const float*)d_in[5];
    const float* gmW    = (const float*)d_in[6];
    const float* gmB    = (const float*)d_in[7];
    const float* bnxw   = (const float*)d_in[8];
    const float* bnxb   = (const float*)d_in[9];
    const float* bnyw   = (const float*)d_in[10];
    const float* bnyb   = (const float*)d_in[11];
    const int* src_g    = (const int*)d_in[12];
    const int* dst_g    = (const int*)d_in[13];
    const int* src_lg   = (const int*)d_in[14];
    const int* dst_lg   = (const int*)d_in[15];
    const int* eid      = (const int*)d_in[16];

    int N  = in_sizes[2];
    int E  = in_sizes[3];
    int EL = in_sizes[14];

    float *p_yx, *p_x1, *p_x2, *p_x4, *p_xt;
    float *p_ya, *p_y1, *p_y2, *p_y4, *p_coef;
    __half *p_y1h, *p_y2h, *p_t3h;
    int *p_cnt_g, *p_rp_g, *p_bs_g, *p_cnt_lg, *p_rp_lg, *p_bs_lg;
    int *p_slots_lg, *p_slots_nid;
    int2* p_slots_g;
    double* p_stats;
    cudaGetSymbolAddress((void**)&p_yx, g_yx);
    cudaGetSymbolAddress((void**)&p_x1, g_x1);
    cudaGetSymbolAddress((void**)&p_x2, g_x2);
    cudaGetSymbolAddress((void**)&p_x4, g_x4);
    cudaGetSymbolAddress((void**)&p_xt, g_xt);
    cudaGetSymbolAddress((void**)&p_ya, g_ya);
    cudaGetSymbolAddress((void**)&p_y1, g_y1);
    cudaGetSymbolAddress((void**)&p_y2, g_y2);
    cudaGetSymbolAddress((void**)&p_y4, g_y4);
    cudaGetSymbolAddress((void**)&p_y1h, g_y1h);
    cudaGetSymbolAddress((void**)&p_y2h, g_y2h);
    cudaGetSymbolAddress((void**)&p_t3h, g_t3h);
    cudaGetSymbolAddress((void**)&p_cnt_g, g_cnt_g);
    cudaGetSymbolAddress((void**)&p_rp_g, g_rowptr_g);
    cudaGetSymbolAddress((void**)&p_bs_g, g_bsum_g);
    cudaGetSymbolAddress((void**)&p_slots_g, g_slots_g);
    cudaGetSymbolAddress((void**)&p_cnt_lg, g_cnt_lg);
    cudaGetSymbolAddress((void**)&p_rp_lg, g_rowptr_lg);
    cudaGetSymbolAddress((void**)&p_bs_lg, g_bsum_lg);
    cudaGetSymbolAddress((void**)&p_slots_lg, g_slots_lg);
    cudaGetSymbolAddress((void**)&p_slots_nid, g_slots_nid);
    cudaGetSymbolAddress((void**)&p_stats, g_stats);
    cudaGetSymbolAddress((void**)&p_coef, g_coef);

    float* ox = (float*)d_out;
    float* oy = ox + (size_t)N * 16;

    const int TB = 256;
    int rp_g  = (N + 4095) & ~4095;
    int rp_lg = (E + 4095) & ~4095;
    int nb_g  = rp_g  / 4096;
    int nb_lg = rp_lg / 4096;

    cudaMemsetAsync(p_stats, 0, 64 * sizeof(double));

    // ---- node-graph: padded CSR ----
    cudaMemsetAsync(p_cnt_g, 0, (size_t)rp_g * 4);
    k_hist<<<cdiv(E, TB), TB>>>(dst_g, p_cnt_g, E);
    k_scan1<<<nb_g, TB>>>(p_cnt_g, p_bs_g);
    k_scan2<<<1, 1024>>>(p_bs_g, nb_g);
    k_scan3<<<nb_g, TB>>>(p_cnt_g, p_bs_g, p_rp_g, rp_g);
    k_pad_g<<<cdiv(N, TB), TB>>>(p_cnt_g, p_rp_g, p_slots_g, N);
    cudaMemsetAsync(p_cnt_g, 0, (size_t)rp_g * 4);
    k_fill_g<<<cdiv(E, TB), TB>>>(src_g, dst_g, p_rp_g, p_cnt_g, p_slots_g, E);

    // ---- line-graph: padded CSR + precomputed nid ----
    cudaMemsetAsync(p_cnt_lg, 0, (size_t)rp_lg * 4);
    k_hist<<<cdiv(EL, TB), TB>>>(dst_lg, p_cnt_lg, EL);
    k_scan1<<<nb_lg, TB>>>(p_cnt_lg, p_bs_lg);
    k_scan2<<<1, 1024>>>(p_bs_lg, nb_lg);
    k_scan3<<<nb_lg, TB>>>(p_cnt_lg, p_bs_lg, p_rp_lg, rp_lg);
    k_pad_lg<<<cdiv(E, TB), TB>>>(p_cnt_lg, p_rp_lg, p_slots_lg, p_slots_nid, E);
    cudaMemsetAsync(p_cnt_lg, 0, (size_t)rp_lg * 4);
    k_fill_lg<<<cdiv(EL, TB), TB>>>(src_lg, dst_lg, eid, p_rp_lg, p_cnt_lg,
                                    p_slots_lg, p_slots_nid, EL);

    // ---- node branch ----
    k_node_pass1<<<cdiv((long)N * 4, TB), TB>>>(x, y, p_rp_g, p_slots_g, p_x1, p_yx, N);
    k_spmm_csr2<<<cdiv((long)N * 4, TB), TB>>>(p_x1, p_rp_g, p_slots_g, p_x2, N);
    k_spmm_csr2<<<cdiv((long)N * 4, TB), TB>>>(p_x2, p_rp_g, p_slots_g, p_xt, N);
    k_spmm_csr2<<<cdiv((long)N * 4, TB), TB>>>(p_xt, p_rp_g, p_slots_g, p_x4, N);
    k_combine<<<cdiv(N, TB), TB>>>(x, deg_g, p_yx, p_x1, p_x2, p_x4, thW, thB, ox, p_stats, N);
    k_bnprep<<<1, 16>>>(p_stats, bnxw, bnxb, p_coef, (double)N);
    k_bn<<<cdiv((long)N * 4, TB), TB>>>(ox, p_coef, (long)N * 4);

    // ---- line (edge) branch: fp16 gather chain ----
    k_line_pass1<<<cdiv((long)E * 4, TB), TB>>>(y, x, p_rp_lg, p_slots_lg, p_slots_nid,
                                                p_y1, p_ya, p_y1h, E);
    {
        long h2 = (long)E * 2;
        k_spmm_h<<<cdiv(h2, TB), TB>>>(p_y1h, p_rp_lg, p_slots_lg, p_y2, p_y2h, E);      // A^2 y
        k_spmm_h<<<cdiv(h2, TB), TB>>>(p_y2h, p_rp_lg, p_slots_lg, (float*)0, p_t3h, E); // A^3 y (h only)
        k_spmm_h<<<cdiv(h2, TB), TB>>>(p_t3h, p_rp_lg, p_slots_lg, p_y4, (__half*)0, E); // A^4 y
    }
    k_combine<<<cdiv(E, TB), TB>>>(y, deg_lg, p_ya, p_y1, p_y2, p_y4, gmW, gmB, oy, p_stats + 32, E);
    k_bnprep<<<1, 16>>>(p_stats + 32, bnyw, bnyb, p_coef + 32, (double)E);
    k_bn<<<cdiv((long)E * 4, TB), TB>>>(oy, p_coef + 32, (long)E * 4);
}